// round 1
// baseline (speedup 1.0000x reference)
#include <cuda_runtime.h>
#include <math.h>

#define M_ROWS 36928   // B*T = 64*577
#define E_DIM  768
#define H_DIM  64
#define T_LEN  577
#define B_SZ   64
#define GW     24

// scratch (static device arrays; no allocation)
__device__ float g_q[M_ROWS * H_DIM];
__device__ float g_k[M_ROWS * H_DIM];
__device__ float g_v[M_ROWS * H_DIM];

// ---------------------------------------------------------------------------
// Kernel 1: fused QKV projection + LayerNorm epilogue
// grid (289, 3): gy selects {q,k,v}. BM=128, BN=64, BK=16, 256 threads, 8x4 tile
// ---------------------------------------------------------------------------
__global__ __launch_bounds__(256) void qkv_ln_kernel(
    const float* __restrict__ x,
    const float* __restrict__ w_q, const float* __restrict__ w_k, const float* __restrict__ w_v,
    const float* __restrict__ q_gamma, const float* __restrict__ q_beta,
    const float* __restrict__ k_gamma, const float* __restrict__ k_beta)
{
    const int which = blockIdx.y;
    const float* __restrict__ w = (which == 0) ? w_q : (which == 1) ? w_k : w_v;
    float* __restrict__ outg = (which == 0) ? g_q : (which == 1) ? g_k : g_v;
    const float* __restrict__ gamma = (which == 0) ? q_gamma : k_gamma;
    const float* __restrict__ beta  = (which == 0) ? q_beta  : k_beta;

    // phase 1: x_s[16][132] (transposed) + w_s[16][68]  = 3200 floats
    // epilogue: out_s[128][65]                          = 8320 floats
    __shared__ float smem[128 * 65];
    __shared__ float mu_s[128], rstd_s[128];
    float* x_s = smem;               // [16][132]
    float* w_s = smem + 16 * 132;    // [16][68]

    const int m0  = blockIdx.x * 128;
    const int tid = threadIdx.x;
    const int ty  = tid >> 4;        // 0..15 -> 8 rows each
    const int tx  = tid & 15;        // 0..15 -> 4 cols each

    float acc[8][4];
#pragma unroll
    for (int i = 0; i < 8; i++)
#pragma unroll
        for (int j = 0; j < 4; j++) acc[i][j] = 0.f;

    for (int k0 = 0; k0 < E_DIM; k0 += 16) {
        // load x tile (transposed into smem)
#pragma unroll
        for (int i = tid; i < 128 * 16; i += 256) {
            int r = i >> 4, c = i & 15;
            int m = m0 + r;
            float vx = (m < M_ROWS) ? x[(size_t)m * E_DIM + k0 + c] : 0.f;
            x_s[c * 132 + r] = vx;
        }
        // load w tile
#pragma unroll
        for (int i = tid; i < 16 * 64; i += 256) {
            int r = i >> 6, c = i & 63;
            w_s[r * 68 + c] = w[(k0 + r) * H_DIM + c];
        }
        __syncthreads();
#pragma unroll
        for (int j = 0; j < 16; j++) {
            float4 xv0 = *(const float4*)&x_s[j * 132 + ty * 8];
            float4 xv1 = *(const float4*)&x_s[j * 132 + ty * 8 + 4];
            float4 wv  = *(const float4*)&w_s[j * 68 + tx * 4];
            float xr[8] = {xv0.x, xv0.y, xv0.z, xv0.w, xv1.x, xv1.y, xv1.z, xv1.w};
            float wr[4] = {wv.x, wv.y, wv.z, wv.w};
#pragma unroll
            for (int i = 0; i < 8; i++)
#pragma unroll
                for (int jj = 0; jj < 4; jj++)
                    acc[i][jj] += xr[i] * wr[jj];
        }
        __syncthreads();
    }

    // epilogue: stage tile in smem, LayerNorm per row (full H=64 in-block)
    float* out_s = smem;   // [128][65]
#pragma unroll
    for (int i = 0; i < 8; i++)
#pragma unroll
        for (int jj = 0; jj < 4; jj++)
            out_s[(ty * 8 + i) * 65 + tx * 4 + jj] = acc[i][jj];
    __syncthreads();

    if (which < 2) {
        if (tid < 128) {
            int r = tid;
            if (m0 + r < M_ROWS) {
                float s = 0.f;
#pragma unroll 8
                for (int c = 0; c < 64; c++) s += out_s[r * 65 + c];
                float mu = s * (1.f / 64.f);
                float v2 = 0.f;
#pragma unroll 8
                for (int c = 0; c < 64; c++) {
                    float d = out_s[r * 65 + c] - mu;
                    v2 += d * d;
                }
                mu_s[r]   = mu;
                rstd_s[r] = rsqrtf(v2 * (1.f / 64.f) + 1e-5f);
            }
        }
        __syncthreads();
    }

#pragma unroll
    for (int i = tid; i < 128 * 64; i += 256) {
        int r = i >> 6, c = i & 63;
        int m = m0 + r;
        if (m < M_ROWS) {
            float val = out_s[r * 65 + c];
            if (which < 2)
                val = (val - mu_s[r]) * rstd_s[r] * gamma[c] + beta[c];
            outg[(size_t)m * H_DIM + c] = val;
        }
    }
}

// ---------------------------------------------------------------------------
// Kernel 2: flash-style attention with fused Gaussian augmentation
// grid (10, 64): bx = 64-row q tile, by = batch. 256 threads (16x16), 4x4 tiles
// ---------------------------------------------------------------------------
#define ATTN_SMEM_FLOATS (3 * 64 * 68 + 64 * 65 + 6 * 64)
#define ATTN_SMEM_BYTES  (ATTN_SMEM_FLOATS * 4)

__global__ __launch_bounds__(256) void attn_kernel(
    const float* __restrict__ w_sigma, const float* __restrict__ b_sigma,
    const float* __restrict__ w_alpha, const float* __restrict__ b_alpha,
    float* __restrict__ out)
{
    extern __shared__ float sm[];
    float* q_s = sm;                    // [64][68]
    float* k_s = q_s + 64 * 68;         // [64][68]
    float* v_s = k_s + 64 * 68;         // [64][68]
    float* p_s = v_s + 64 * 68;         // [64][65]
    float* m_s  = p_s + 64 * 65;
    float* l_s  = m_s + 64;
    float* sc_s = l_s + 64;
    float* al_s = sc_s + 64;
    float* ix_s = al_s + 64;
    float* iy_s = ix_s + 64;

    const int b   = blockIdx.y;
    const int q0  = blockIdx.x * 64;
    const int tid = threadIdx.x;
    const int ty  = tid >> 4, tx = tid & 15;
    const size_t base = (size_t)b * T_LEN * H_DIM;

    // load q tile
#pragma unroll
    for (int i = tid; i < 64 * 64; i += 256) {
        int r = i >> 6, c = i & 63;
        int qi = q0 + r;
        q_s[r * 68 + c] = (qi < T_LEN) ? g_q[base + (size_t)qi * H_DIM + c] : 0.f;
    }
    __syncthreads();

    // per-q-row augmentation params: alpha = softplus(q.w_a+b), sigma = sigmoid(q.w_s+b)
    if (tid < 64) {
        int r = tid;
        int qi = q0 + r;
        m_s[r] = -1e30f;
        l_s[r] = 0.f;
        if (qi >= 1 && qi < T_LEN) {
            float a = 0.f, s0 = 0.f, s1 = 0.f;
#pragma unroll 8
            for (int c = 0; c < 64; c++) {
                float qv = q_s[r * 68 + c];
                a  += qv * w_alpha[c];
                s0 += qv * w_sigma[c * 2 + 0];
                s1 += qv * w_sigma[c * 2 + 1];
            }
            a += b_alpha[0]; s0 += b_sigma[0]; s1 += b_sigma[1];
            float alpha = fmaxf(a, 0.f) + log1pf(expf(-fabsf(a)));
            float sx = 1.f / (1.f + expf(-s0));
            float sy = 1.f / (1.f + expf(-s1));
            al_s[r] = alpha;
            ix_s[r] = 0.5f / (sx * sx);
            iy_s[r] = 0.5f / (sy * sy);
        } else {
            al_s[r] = 0.f; ix_s[r] = 0.f; iy_s[r] = 0.f;
        }
    }
    __syncthreads();

    float oacc[4][4];
#pragma unroll
    for (int i = 0; i < 4; i++)
#pragma unroll
        for (int j = 0; j < 4; j++) oacc[i][j] = 0.f;

    for (int k0 = 0; k0 < T_LEN; k0 += 64) {
        // load K/V tile
#pragma unroll
        for (int i = tid; i < 64 * 64; i += 256) {
            int r = i >> 6, c = i & 63;
            int ki = k0 + r;
            bool ok = ki < T_LEN;
            k_s[r * 68 + c] = ok ? g_k[base + (size_t)ki * H_DIM + c] : 0.f;
            v_s[r * 68 + c] = ok ? g_v[base + (size_t)ki * H_DIM + c] : 0.f;
        }
        __syncthreads();

        // sim tile: 4x4 per thread, float4 along H
        float s[4][4];
#pragma unroll
        for (int i = 0; i < 4; i++)
#pragma unroll
            for (int j = 0; j < 4; j++) s[i][j] = 0.f;
#pragma unroll 4
        for (int j4 = 0; j4 < 16; j4++) {
            float4 qv[4], kv[4];
#pragma unroll
            for (int i = 0; i < 4; i++)
                qv[i] = *(const float4*)&q_s[(ty * 4 + i) * 68 + j4 * 4];
#pragma unroll
            for (int i = 0; i < 4; i++)
                kv[i] = *(const float4*)&k_s[(tx * 4 + i) * 68 + j4 * 4];
#pragma unroll
            for (int iq = 0; iq < 4; iq++)
#pragma unroll
                for (int ik = 0; ik < 4; ik++)
                    s[iq][ik] += qv[iq].x * kv[ik].x + qv[iq].y * kv[ik].y +
                                 qv[iq].z * kv[ik].z + qv[iq].w * kv[ik].w;
        }

        // Gaussian augmentation + scale + stage logits
#pragma unroll
        for (int ik = 0; ik < 4; ik++) {
            int ki = k0 + tx * 4 + ik;
            bool kvalid = ki < T_LEN;
            float kgx = 0.f, kgy = 0.f;
            if (ki >= 1) {
                int g = ki - 1;
                kgx = (float)(g % GW);
                kgy = (float)(g / GW);
            }
#pragma unroll
            for (int iq = 0; iq < 4; iq++) {
                int r = ty * 4 + iq;
                int qi = q0 + r;
                float val = s[iq][ik];
                if (qi >= 1 && qi < T_LEN && ki >= 1 && kvalid) {
                    int gq = qi - 1;
                    float dgx = (float)(gq % GW) - kgx;
                    float dgy = (float)(gq / GW) - kgy;
                    val += al_s[r] * __expf(-dgx * dgx * ix_s[r] - dgy * dgy * iy_s[r]);
                }
                val *= 0.125f;                 // 1/sqrt(H), H=64
                if (!kvalid) val = -1e30f;
                p_s[r * 65 + tx * 4 + ik] = val;
            }
        }
        __syncthreads();

        // online softmax update per row
        if (tid < 64) {
            int r = tid;
            float mold = m_s[r];
            float mnew = mold;
#pragma unroll 8
            for (int c = 0; c < 64; c++) mnew = fmaxf(mnew, p_s[r * 65 + c]);
            float scf = __expf(mold - mnew);
            float sum = 0.f;
#pragma unroll 8
            for (int c = 0; c < 64; c++) {
                float e = __expf(p_s[r * 65 + c] - mnew);
                p_s[r * 65 + c] = e;
                sum += e;
            }
            l_s[r]  = l_s[r] * scf + sum;
            m_s[r]  = mnew;
            sc_s[r] = scf;
        }
        __syncthreads();

        // rescale accumulators + P@V
#pragma unroll
        for (int iq = 0; iq < 4; iq++) {
            float f = sc_s[ty * 4 + iq];
#pragma unroll
            for (int ih = 0; ih < 4; ih++) oacc[iq][ih] *= f;
        }
#pragma unroll 4
        for (int kc = 0; kc < 64; kc++) {
            float4 vv = *(const float4*)&v_s[kc * 68 + tx * 4];
#pragma unroll
            for (int iq = 0; iq < 4; iq++) {
                float p = p_s[(ty * 4 + iq) * 65 + kc];
                oacc[iq][0] += p * vv.x;
                oacc[iq][1] += p * vv.y;
                oacc[iq][2] += p * vv.z;
                oacc[iq][3] += p * vv.w;
            }
        }
        __syncthreads();
    }

    // final normalize + write
#pragma unroll
    for (int iq = 0; iq < 4; iq++) {
        int r = ty * 4 + iq;
        int qi = q0 + r;
        if (qi < T_LEN) {
            float inv = 1.f / l_s[r];
            float4 o;
            o.x = oacc[iq][0] * inv;
            o.y = oacc[iq][1] * inv;
            o.z = oacc[iq][2] * inv;
            o.w = oacc[iq][3] * inv;
            *(float4*)&out[base + (size_t)qi * H_DIM + tx * 4] = o;
        }
    }
}

// ---------------------------------------------------------------------------
extern "C" void kernel_launch(void* const* d_in, const int* in_sizes, int n_in,
                              void* d_out, int out_size)
{
    const float* x       = (const float*)d_in[0];
    const float* w_q     = (const float*)d_in[1];
    const float* w_k     = (const float*)d_in[2];
    const float* w_v     = (const float*)d_in[3];
    const float* q_gamma = (const float*)d_in[4];
    const float* q_beta  = (const float*)d_in[5];
    const float* k_gamma = (const float*)d_in[6];
    const float* k_beta  = (const float*)d_in[7];
    const float* w_sigma = (const float*)d_in[8];
    const float* b_sigma = (const float*)d_in[9];
    const float* w_alpha = (const float*)d_in[10];
    const float* b_alpha = (const float*)d_in[11];
    float* out = (float*)d_out;

    dim3 grid1((M_ROWS + 127) / 128, 3);
    qkv_ln_kernel<<<grid1, 256>>>(x, w_q, w_k, w_v, q_gamma, q_beta, k_gamma, k_beta);

    cudaFuncSetAttribute(attn_kernel, cudaFuncAttributeMaxDynamicSharedMemorySize,
                         ATTN_SMEM_BYTES);
    dim3 grid2((T_LEN + 63) / 64, B_SZ);
    attn_kernel<<<grid2, 256, ATTN_SMEM_BYTES>>>(w_sigma, b_sigma, w_alpha, b_alpha, out);
}

// round 2
// speedup vs baseline: 1.0211x; 1.0211x over previous
#include <cuda_runtime.h>
#include <math.h>

#define M_ROWS 36928   // B*T = 64*577
#define E_DIM  768
#define H_DIM  64
#define T_LEN  577
#define B_SZ   64
#define GW     24

// scratch (static device arrays; no allocation)
__device__ float g_q[M_ROWS * H_DIM];
__device__ float g_k[M_ROWS * H_DIM];
__device__ float g_v[M_ROWS * H_DIM];

// ---------------------------------------------------------------------------
// Kernel 1: fused QKV projection + LayerNorm epilogue (unchanged — near FFMA peak)
// ---------------------------------------------------------------------------
__global__ __launch_bounds__(256) void qkv_ln_kernel(
    const float* __restrict__ x,
    const float* __restrict__ w_q, const float* __restrict__ w_k, const float* __restrict__ w_v,
    const float* __restrict__ q_gamma, const float* __restrict__ q_beta,
    const float* __restrict__ k_gamma, const float* __restrict__ k_beta)
{
    const int which = blockIdx.y;
    const float* __restrict__ w = (which == 0) ? w_q : (which == 1) ? w_k : w_v;
    float* __restrict__ outg = (which == 0) ? g_q : (which == 1) ? g_k : g_v;
    const float* __restrict__ gamma = (which == 0) ? q_gamma : k_gamma;
    const float* __restrict__ beta  = (which == 0) ? q_beta  : k_beta;

    __shared__ float smem[128 * 65];
    __shared__ float mu_s[128], rstd_s[128];
    float* x_s = smem;               // [16][132]
    float* w_s = smem + 16 * 132;    // [16][68]

    const int m0  = blockIdx.x * 128;
    const int tid = threadIdx.x;
    const int ty  = tid >> 4;
    const int tx  = tid & 15;

    float acc[8][4];
#pragma unroll
    for (int i = 0; i < 8; i++)
#pragma unroll
        for (int j = 0; j < 4; j++) acc[i][j] = 0.f;

    for (int k0 = 0; k0 < E_DIM; k0 += 16) {
#pragma unroll
        for (int i = tid; i < 128 * 16; i += 256) {
            int r = i >> 4, c = i & 15;
            int m = m0 + r;
            float vx = (m < M_ROWS) ? x[(size_t)m * E_DIM + k0 + c] : 0.f;
            x_s[c * 132 + r] = vx;
        }
#pragma unroll
        for (int i = tid; i < 16 * 64; i += 256) {
            int r = i >> 6, c = i & 63;
            w_s[r * 68 + c] = w[(k0 + r) * H_DIM + c];
        }
        __syncthreads();
#pragma unroll
        for (int j = 0; j < 16; j++) {
            float4 xv0 = *(const float4*)&x_s[j * 132 + ty * 8];
            float4 xv1 = *(const float4*)&x_s[j * 132 + ty * 8 + 4];
            float4 wv  = *(const float4*)&w_s[j * 68 + tx * 4];
            float xr[8] = {xv0.x, xv0.y, xv0.z, xv0.w, xv1.x, xv1.y, xv1.z, xv1.w};
            float wr[4] = {wv.x, wv.y, wv.z, wv.w};
#pragma unroll
            for (int i = 0; i < 8; i++)
#pragma unroll
                for (int jj = 0; jj < 4; jj++)
                    acc[i][jj] += xr[i] * wr[jj];
        }
        __syncthreads();
    }

    float* out_s = smem;   // [128][65]
#pragma unroll
    for (int i = 0; i < 8; i++)
#pragma unroll
        for (int jj = 0; jj < 4; jj++)
            out_s[(ty * 8 + i) * 65 + tx * 4 + jj] = acc[i][jj];
    __syncthreads();

    if (which < 2) {
        if (tid < 128) {
            int r = tid;
            if (m0 + r < M_ROWS) {
                float s = 0.f;
#pragma unroll 8
                for (int c = 0; c < 64; c++) s += out_s[r * 65 + c];
                float mu = s * (1.f / 64.f);
                float v2 = 0.f;
#pragma unroll 8
                for (int c = 0; c < 64; c++) {
                    float d = out_s[r * 65 + c] - mu;
                    v2 += d * d;
                }
                mu_s[r]   = mu;
                rstd_s[r] = rsqrtf(v2 * (1.f / 64.f) + 1e-5f);
            }
        }
        __syncthreads();
    }

#pragma unroll
    for (int i = tid; i < 128 * 64; i += 256) {
        int r = i >> 6, c = i & 63;
        int m = m0 + r;
        if (m < M_ROWS) {
            float val = out_s[r * 65 + c];
            if (which < 2)
                val = (val - mu_s[r]) * rstd_s[r] * gamma[c] + beta[c];
            outg[(size_t)m * H_DIM + c] = val;
        }
    }
}

// ---------------------------------------------------------------------------
// Kernel 2: flash attention w/ fused Gaussian aug — register softmax (shuffles)
// grid (10, 64). 256 threads: ty=tid>>4 row-group, tx=tid&15 col-group, 4x4 tile
// ---------------------------------------------------------------------------
#define ATTN_SMEM_FLOATS (4 * 64 * 68 + 3 * 64)
#define ATTN_SMEM_BYTES  (ATTN_SMEM_FLOATS * 4)

__global__ __launch_bounds__(256) void attn_kernel(
    const float* __restrict__ w_sigma, const float* __restrict__ b_sigma,
    const float* __restrict__ w_alpha, const float* __restrict__ b_alpha,
    float* __restrict__ out)
{
    extern __shared__ float sm[];
    float* q_s = sm;                    // [64][68]
    float* k_s = q_s + 64 * 68;         // [64][68]
    float* v_s = k_s + 64 * 68;         // [64][68]
    float* p_s = v_s + 64 * 68;         // [64][68]
    float* al_s = p_s + 64 * 68;        // [64]
    float* ix_s = al_s + 64;
    float* iy_s = ix_s + 64;

    const int b   = blockIdx.y;
    const int q0  = blockIdx.x * 64;
    const int tid = threadIdx.x;
    const int ty  = tid >> 4, tx = tid & 15;
    const size_t base = (size_t)b * T_LEN * H_DIM;

    // load q tile (float4)
#pragma unroll
    for (int i = 0; i < 4; i++) {
        int f4 = tid + i * 256;               // 0..1023
        int r = f4 >> 4, c4 = f4 & 15;
        int qi = q0 + r;
        float4 qv = (qi < T_LEN) ? *(const float4*)&g_q[base + (size_t)qi * H_DIM + c4 * 4]
                                 : make_float4(0.f, 0.f, 0.f, 0.f);
        *(float4*)&q_s[r * 68 + c4 * 4] = qv;
    }
    __syncthreads();

    // per-q-row augmentation params (once per block)
    if (tid < 64) {
        int r = tid;
        int qi = q0 + r;
        if (qi >= 1 && qi < T_LEN) {
            float a = 0.f, s0 = 0.f, s1 = 0.f;
#pragma unroll 8
            for (int c = 0; c < 64; c++) {
                float qv = q_s[r * 68 + c];
                a  += qv * w_alpha[c];
                s0 += qv * w_sigma[c * 2 + 0];
                s1 += qv * w_sigma[c * 2 + 1];
            }
            a += b_alpha[0]; s0 += b_sigma[0]; s1 += b_sigma[1];
            float alpha = fmaxf(a, 0.f) + log1pf(expf(-fabsf(a)));
            float sx = 1.f / (1.f + expf(-s0));
            float sy = 1.f / (1.f + expf(-s1));
            al_s[r] = alpha;
            ix_s[r] = 0.5f / (sx * sx);
            iy_s[r] = 0.5f / (sy * sy);
        } else {
            al_s[r] = 0.f; ix_s[r] = 0.f; iy_s[r] = 0.f;
        }
    }
    __syncthreads();

    // per-row register state (replicated across the 16 tx lanes of a ty group)
    float m_i[4], l_i[4];
    float alr[4], ixr[4], iyr[4], qgx[4], qgy[4];
    bool  qaug[4];
#pragma unroll
    for (int iq = 0; iq < 4; iq++) {
        int r = ty * 4 + iq;
        int qi = q0 + r;
        m_i[iq] = -1e30f;
        l_i[iq] = 0.f;
        alr[iq] = al_s[r]; ixr[iq] = ix_s[r]; iyr[iq] = iy_s[r];
        qaug[iq] = (qi >= 1 && qi < T_LEN);
        int gq = (qi >= 1) ? qi - 1 : 0;
        qgx[iq] = (float)(gq % GW);
        qgy[iq] = (float)(gq / GW);
    }

    float oacc[4][4];
#pragma unroll
    for (int i = 0; i < 4; i++)
#pragma unroll
        for (int j = 0; j < 4; j++) oacc[i][j] = 0.f;

    for (int k0 = 0; k0 < T_LEN; k0 += 64) {
        // load K/V tile (float4)
#pragma unroll
        for (int i = 0; i < 4; i++) {
            int f4 = tid + i * 256;
            int r = f4 >> 4, c4 = f4 & 15;
            int ki = k0 + r;
            float4 kv = make_float4(0.f, 0.f, 0.f, 0.f);
            float4 vv = kv;
            if (ki < T_LEN) {
                kv = *(const float4*)&g_k[base + (size_t)ki * H_DIM + c4 * 4];
                vv = *(const float4*)&g_v[base + (size_t)ki * H_DIM + c4 * 4];
            }
            *(float4*)&k_s[r * 68 + c4 * 4] = kv;
            *(float4*)&v_s[r * 68 + c4 * 4] = vv;
        }
        __syncthreads();

        // sim tile: 4x4 per thread
        float s[4][4];
#pragma unroll
        for (int i = 0; i < 4; i++)
#pragma unroll
            for (int j = 0; j < 4; j++) s[i][j] = 0.f;
#pragma unroll 4
        for (int j4 = 0; j4 < 16; j4++) {
            float4 qv[4], kv[4];
#pragma unroll
            for (int i = 0; i < 4; i++)
                qv[i] = *(const float4*)&q_s[(ty * 4 + i) * 68 + j4 * 4];
#pragma unroll
            for (int i = 0; i < 4; i++)
                kv[i] = *(const float4*)&k_s[(tx * 4 + i) * 68 + j4 * 4];
#pragma unroll
            for (int iq = 0; iq < 4; iq++)
#pragma unroll
                for (int ik = 0; ik < 4; ik++)
                    s[iq][ik] += qv[iq].x * kv[ik].x + qv[iq].y * kv[ik].y +
                                 qv[iq].z * kv[ik].z + qv[iq].w * kv[ik].w;
        }

        // Gaussian augmentation + scale + mask (registers only)
#pragma unroll
        for (int ik = 0; ik < 4; ik++) {
            int ki = k0 + tx * 4 + ik;
            bool kvalid = (ki < T_LEN);
            bool kaug = (ki >= 1) && kvalid;
            int g = kaug ? ki - 1 : 0;
            float kgx = (float)(g % GW);
            float kgy = (float)(g / GW);
#pragma unroll
            for (int iq = 0; iq < 4; iq++) {
                float val = s[iq][ik];
                if (kaug && qaug[iq]) {
                    float dgx = qgx[iq] - kgx;
                    float dgy = qgy[iq] - kgy;
                    val += alr[iq] * __expf(-dgx * dgx * ixr[iq] - dgy * dgy * iyr[iq]);
                }
                val *= 0.125f;
                if (!kvalid) val = -1e30f;
                s[iq][ik] = val;
            }
        }

        // register softmax: row max/sum via shuffle over 16 tx lanes
        float mloc[4];
#pragma unroll
        for (int iq = 0; iq < 4; iq++)
            mloc[iq] = fmaxf(fmaxf(s[iq][0], s[iq][1]), fmaxf(s[iq][2], s[iq][3]));
#pragma unroll
        for (int o = 8; o >= 1; o >>= 1)
#pragma unroll
            for (int iq = 0; iq < 4; iq++)
                mloc[iq] = fmaxf(mloc[iq], __shfl_xor_sync(0xffffffffu, mloc[iq], o));

        float rs[4];
#pragma unroll
        for (int iq = 0; iq < 4; iq++) {
            float mnew = fmaxf(m_i[iq], mloc[iq]);
            float scf = __expf(m_i[iq] - mnew);
            m_i[iq] = mnew;
            float sum = 0.f;
#pragma unroll
            for (int ik = 0; ik < 4; ik++) {
                float p = __expf(s[iq][ik] - mnew);
                s[iq][ik] = p;
                sum += p;
            }
            rs[iq] = sum;
            l_i[iq] *= scf;
#pragma unroll
            for (int ih = 0; ih < 4; ih++) oacc[iq][ih] *= scf;
        }
#pragma unroll
        for (int o = 8; o >= 1; o >>= 1)
#pragma unroll
            for (int iq = 0; iq < 4; iq++)
                rs[iq] += __shfl_xor_sync(0xffffffffu, rs[iq], o);
#pragma unroll
        for (int iq = 0; iq < 4; iq++) l_i[iq] += rs[iq];

        // stage P (exp'd) to smem — one float4 per row
#pragma unroll
        for (int iq = 0; iq < 4; iq++)
            *(float4*)&p_s[(ty * 4 + iq) * 68 + tx * 4] =
                make_float4(s[iq][0], s[iq][1], s[iq][2], s[iq][3]);
        __syncthreads();

        // P @ V with float4 loads
#pragma unroll 2
        for (int kc4 = 0; kc4 < 16; kc4++) {
            float4 pr[4], vv[4];
#pragma unroll
            for (int iq = 0; iq < 4; iq++)
                pr[iq] = *(const float4*)&p_s[(ty * 4 + iq) * 68 + kc4 * 4];
#pragma unroll
            for (int j = 0; j < 4; j++)
                vv[j] = *(const float4*)&v_s[(kc4 * 4 + j) * 68 + tx * 4];
#pragma unroll
            for (int iq = 0; iq < 4; iq++) {
                oacc[iq][0] += pr[iq].x * vv[0].x + pr[iq].y * vv[1].x +
                               pr[iq].z * vv[2].x + pr[iq].w * vv[3].x;
                oacc[iq][1] += pr[iq].x * vv[0].y + pr[iq].y * vv[1].y +
                               pr[iq].z * vv[2].y + pr[iq].w * vv[3].y;
                oacc[iq][2] += pr[iq].x * vv[0].z + pr[iq].y * vv[1].z +
                               pr[iq].z * vv[2].z + pr[iq].w * vv[3].z;
                oacc[iq][3] += pr[iq].x * vv[0].w + pr[iq].y * vv[1].w +
                               pr[iq].z * vv[2].w + pr[iq].w * vv[3].w;
            }
        }
        __syncthreads();
    }

    // final normalize + write
#pragma unroll
    for (int iq = 0; iq < 4; iq++) {
        int r = ty * 4 + iq;
        int qi = q0 + r;
        if (qi < T_LEN) {
            float inv = 1.f / l_i[iq];
            float4 o;
            o.x = oacc[iq][0] * inv;
            o.y = oacc[iq][1] * inv;
            o.z = oacc[iq][2] * inv;
            o.w = oacc[iq][3] * inv;
            *(float4*)&out[base + (size_t)qi * H_DIM + tx * 4] = o;
        }
    }
}

// ---------------------------------------------------------------------------
extern "C" void kernel_launch(void* const* d_in, const int* in_sizes, int n_in,
                              void* d_out, int out_size)
{
    const float* x       = (const float*)d_in[0];
    const float* w_q     = (const float*)d_in[1];
    const float* w_k     = (const float*)d_in[2];
    const float* w_v     = (const float*)d_in[3];
    const float* q_gamma = (const float*)d_in[4];
    const float* q_beta  = (const float*)d_in[5];
    const float* k_gamma = (const float*)d_in[6];
    const float* k_beta  = (const float*)d_in[7];
    const float* w_sigma = (const float*)d_in[8];
    const float* b_sigma = (const float*)d_in[9];
    const float* w_alpha = (const float*)d_in[10];
    const float* b_alpha = (const float*)d_in[11];
    float* out = (float*)d_out;

    dim3 grid1((M_ROWS + 127) / 128, 3);
    qkv_ln_kernel<<<grid1, 256>>>(x, w_q, w_k, w_v, q_gamma, q_beta, k_gamma, k_beta);

    cudaFuncSetAttribute(attn_kernel, cudaFuncAttributeMaxDynamicSharedMemorySize,
                         ATTN_SMEM_BYTES);
    dim3 grid2((T_LEN + 63) / 64, B_SZ);
    attn_kernel<<<grid2, 256, ATTN_SMEM_BYTES>>>(w_sigma, b_sigma, w_alpha, b_alpha, out);
}